// round 2
// baseline (speedup 1.0000x reference)
#include <cuda_runtime.h>
#include <cuda_bf16.h>

#define BATCH   8192
#define CLASSES 10000
#define C4      2500          // CLASSES / 4 (float4 units)
#define ROWS_PER_CHUNK 128

__device__ float g_inv_sum[BATCH];
__device__ float g_avg_conf[CLASSES];
__device__ float g_counts[CLASSES];

// ---------------------------------------------------------------- K0: zero accumulators
__global__ void k_zero() {
    int i = blockIdx.x * blockDim.x + threadIdx.x;
    if (i < CLASSES) {
        g_avg_conf[i] = 0.0f;
        g_counts[i]   = 0.0f;
    }
}

// ---------------------------------------------------------------- K1: per-row sum(exp)
// One block per row. Row = 10000 fp32 = 2500 float4 (16B-aligned since 40000%16==0).
__global__ __launch_bounds__(256) void k_rowsum(const float* __restrict__ x) {
    const int r = blockIdx.x;
    const float4* __restrict__ row =
        reinterpret_cast<const float4*>(x + (size_t)r * CLASSES);

    float s = 0.0f;
    for (int i = threadIdx.x; i < C4; i += 256) {
        float4 v = row[i];
        s += __expf(v.x) + __expf(v.y) + __expf(v.z) + __expf(v.w);
    }

    // block reduce (8 warps)
    __shared__ float sm[8];
    #pragma unroll
    for (int o = 16; o; o >>= 1) s += __shfl_down_sync(0xffffffffu, s, o);
    if ((threadIdx.x & 31) == 0) sm[threadIdx.x >> 5] = s;
    __syncthreads();
    if (threadIdx.x < 8) {
        float t = sm[threadIdx.x];
        #pragma unroll
        for (int o = 4; o; o >>= 1) t += __shfl_down_sync(0xffu, t, o);
        if (threadIdx.x == 0) g_inv_sum[r] = 1.0f / t;
    }
}

// ---------------------------------------------------------------- K2: label histogram
// Dtype-robust: the reference says int64, but JAX without x64 silently emits
// int32. Detect int64 little-endian layout (odd int32 words all zero for
// values < 2^32) from the first 16 words; both paths stay within the real
// allocation for their respective dtype.
__global__ void k_hist(const int* __restrict__ tgt) {
    bool is64 = true;
    #pragma unroll
    for (int j = 1; j < 16; j += 2) is64 = is64 && (tgt[j] == 0);

    int i = blockIdx.x * blockDim.x + threadIdx.x;
    if (i < BATCH) {
        int t = is64 ? tgt[2 * i] : tgt[i];
        if (t >= 0 && t < CLASSES) atomicAdd(&g_counts[t], 1.0f);
    }
}

// ---------------------------------------------------------------- K3: column accumulation
// grid.x tiles the 2500 float4 columns (256 per block -> 10 tiles),
// grid.y tiles rows into chunks of ROWS_PER_CHUNK (64 chunks).
// Each thread owns 4 classes; register accumulation; 4 atomics per thread at the end.
__global__ __launch_bounds__(256) void k_cols(const float* __restrict__ x) {
    __shared__ float inv[ROWS_PER_CHUNK];
    const int c4 = blockIdx.x * 256 + threadIdx.x;   // float4 column index
    const int r0 = blockIdx.y * ROWS_PER_CHUNK;

    for (int i = threadIdx.x; i < ROWS_PER_CHUNK; i += 256)
        inv[i] = g_inv_sum[r0 + i];
    __syncthreads();

    if (c4 >= C4) return;

    float4 acc = make_float4(0.f, 0.f, 0.f, 0.f);
    const float4* __restrict__ xp =
        reinterpret_cast<const float4*>(x) + (size_t)r0 * C4 + c4;

    #pragma unroll 4
    for (int r = 0; r < ROWS_PER_CHUNK; r++) {
        float4 v = xp[(size_t)r * C4];
        float is = inv[r];
        acc.x += __expf(v.x) * is;
        acc.y += __expf(v.y) * is;
        acc.z += __expf(v.z) * is;
        acc.w += __expf(v.w) * is;
    }

    const int c = c4 * 4;
    atomicAdd(&g_avg_conf[c + 0], acc.x);
    atomicAdd(&g_avg_conf[c + 1], acc.y);
    atomicAdd(&g_avg_conf[c + 2], acc.z);
    atomicAdd(&g_avg_conf[c + 3], acc.w);
}

// ---------------------------------------------------------------- K4: final L1 reduce
__global__ __launch_bounds__(1024) void k_final(float* __restrict__ out) {
    const float invB = 1.0f / (float)BATCH;
    float s = 0.0f;
    for (int i = threadIdx.x; i < CLASSES; i += 1024)
        s += fabsf((g_avg_conf[i] - g_counts[i]) * invB);

    __shared__ float sm[32];
    #pragma unroll
    for (int o = 16; o; o >>= 1) s += __shfl_down_sync(0xffffffffu, s, o);
    if ((threadIdx.x & 31) == 0) sm[threadIdx.x >> 5] = s;
    __syncthreads();
    if (threadIdx.x < 32) {
        float t = sm[threadIdx.x];
        #pragma unroll
        for (int o = 16; o; o >>= 1) t += __shfl_down_sync(0xffffffffu, t, o);
        if (threadIdx.x == 0) out[0] = t / (float)CLASSES;
    }
}

// ---------------------------------------------------------------- launch
extern "C" void kernel_launch(void* const* d_in, const int* in_sizes, int n_in,
                              void* d_out, int out_size) {
    const float* x   = (const float*)d_in[0];   // [8192, 10000] fp32
    const int*   tgt = (const int*)d_in[1];     // [8192] int32 or int64 (detected)
    float*       out = (float*)d_out;

    k_zero<<<(CLASSES + 255) / 256, 256>>>();
    k_rowsum<<<BATCH, 256>>>(x);
    k_hist<<<(BATCH + 255) / 256, 256>>>(tgt);

    dim3 g3((C4 + 255) / 256, BATCH / ROWS_PER_CHUNK);  // (10, 64)
    k_cols<<<g3, 256>>>(x);

    k_final<<<1, 1024>>>(out);
}

// round 3
// speedup vs baseline: 1.4340x; 1.4340x over previous
#include <cuda_runtime.h>
#include <cuda_fp16.h>

#define BATCH   8192
#define CLASSES 10000
#define C4      2500            // float4 per row
#define ROWS    8               // rows per block
#define THREADS 1024
#define NREP    8               // replica accumulator arrays (reduce atomic contention)
#define SMEM_BYTES (ROWS * CLASSES * 2)   // 160000 B of fp16 exp cache

__device__ float g_part[NREP][CLASSES];
__device__ float g_counts[CLASSES];

// ---------------------------------------------------------------- zero accumulators + out
__global__ void k_zero(float* __restrict__ out) {
    int i = blockIdx.x * blockDim.x + threadIdx.x;
    if (i < CLASSES) {
        g_counts[i] = 0.0f;
        #pragma unroll
        for (int r = 0; r < NREP; r++) g_part[r][i] = 0.0f;
    }
    if (i == 0) out[0] = 0.0f;
}

// ---------------------------------------------------------------- label histogram
// Dtype-robust: detect int64-LE (odd int32 words zero for values < 2^32) vs int32.
__global__ void k_hist(const int* __restrict__ tgt) {
    bool is64 = true;
    #pragma unroll
    for (int j = 1; j < 16; j += 2) is64 = is64 && (tgt[j] == 0);
    int i = blockIdx.x * blockDim.x + threadIdx.x;
    if (i < BATCH) {
        int t = is64 ? tgt[2 * i] : tgt[i];
        if (t >= 0 && t < CLASSES) atomicAdd(&g_counts[t], 1.0f);
    }
}

// ---------------------------------------------------------------- fused single-read kernel
// Block b owns rows [8b, 8b+8). Phase A: read rows once (float4, coalesced),
// compute fp32 exp, cache as fp16 in SMEM, accumulate fp32 row sums.
// Phase B: sweep columns from SMEM, acc = sum_r exp16[r][c] * inv[r], one
// atomicAdd per class per block into a replica array.
__global__ __launch_bounds__(THREADS, 1) void k_main(const float* __restrict__ x) {
    extern __shared__ __half sm_exp[];      // [ROWS][CLASSES]
    __shared__ float wsum[32];
    __shared__ float inv[ROWS];

    const int tid     = threadIdx.x;
    const int r       = tid >> 7;           // 0..7  (128 threads per row)
    const int lane128 = tid & 127;
    const size_t row  = (size_t)blockIdx.x * ROWS + r;

    const float4* __restrict__ rowp =
        reinterpret_cast<const float4*>(x + row * CLASSES);
    // 8-byte stores: two half2 packed as uint2 -> STS.64, conflict-free
    uint2* smrow8 = reinterpret_cast<uint2*>(sm_exp + r * CLASSES);

    float s = 0.0f;
    #pragma unroll 4
    for (int i = lane128; i < C4; i += 128) {
        float4 v = rowp[i];
        float e0 = __expf(v.x), e1 = __expf(v.y);
        float e2 = __expf(v.z), e3 = __expf(v.w);
        s += (e0 + e1) + (e2 + e3);
        __half2 h01 = __floats2half2_rn(e0, e1);
        __half2 h23 = __floats2half2_rn(e2, e3);
        smrow8[i] = make_uint2(*reinterpret_cast<unsigned*>(&h01),
                               *reinterpret_cast<unsigned*>(&h23));
    }

    // reduce 128 threads per row: warp shfl -> 4 warp sums -> combine
    #pragma unroll
    for (int o = 16; o; o >>= 1) s += __shfl_down_sync(0xffffffffu, s, o);
    if ((tid & 31) == 0) wsum[tid >> 5] = s;
    __syncthreads();
    if (tid < ROWS) {
        float t = wsum[4 * tid] + wsum[4 * tid + 1] +
                  wsum[4 * tid + 2] + wsum[4 * tid + 3];
        inv[tid] = 1.0f / t;
    }
    __syncthreads();

    // Phase B: per-class accumulation from SMEM (half2 = 2 classes at a time)
    float iv[ROWS];
    #pragma unroll
    for (int rr = 0; rr < ROWS; rr++) iv[rr] = inv[rr];

    float* __restrict__ dst = g_part[blockIdx.x & (NREP - 1)];
    const __half2* smh2 = reinterpret_cast<const __half2*>(sm_exp);

    for (int j = tid; j < CLASSES / 2; j += THREADS) {
        float a0 = 0.0f, a1 = 0.0f;
        #pragma unroll
        for (int rr = 0; rr < ROWS; rr++) {
            float2 f = __half22float2(smh2[rr * (CLASSES / 2) + j]);
            a0 += f.x * iv[rr];
            a1 += f.y * iv[rr];
        }
        atomicAdd(&dst[2 * j],     a0);
        atomicAdd(&dst[2 * j + 1], a1);
    }
}

// ---------------------------------------------------------------- final L1 reduce
__global__ __launch_bounds__(256) void k_final(float* __restrict__ out) {
    const float invB = 1.0f / (float)BATCH;
    float s = 0.0f;
    for (int c = blockIdx.x * 256 + threadIdx.x; c < CLASSES; c += gridDim.x * 256) {
        float v = 0.0f;
        #pragma unroll
        for (int r = 0; r < NREP; r++) v += g_part[r][c];
        s += fabsf((v - g_counts[c]) * invB);
    }
    __shared__ float sm[8];
    #pragma unroll
    for (int o = 16; o; o >>= 1) s += __shfl_down_sync(0xffffffffu, s, o);
    if ((threadIdx.x & 31) == 0) sm[threadIdx.x >> 5] = s;
    __syncthreads();
    if (threadIdx.x < 8) {
        float t = sm[threadIdx.x];
        #pragma unroll
        for (int o = 4; o; o >>= 1) t += __shfl_down_sync(0xffu, t, o);
        if (threadIdx.x == 0) atomicAdd(out, t / (float)CLASSES);
    }
}

// ---------------------------------------------------------------- launch
extern "C" void kernel_launch(void* const* d_in, const int* in_sizes, int n_in,
                              void* d_out, int out_size) {
    const float* x   = (const float*)d_in[0];   // [8192, 10000] fp32
    const int*   tgt = (const int*)d_in[1];     // [8192] int32 or int64 (detected)
    float*       out = (float*)d_out;

    // 160 KB dynamic smem needs an explicit opt-in (idempotent, capture-safe)
    cudaFuncSetAttribute(k_main, cudaFuncAttributeMaxDynamicSharedMemorySize,
                         SMEM_BYTES);

    k_zero<<<(CLASSES + 255) / 256, 256>>>(out);
    k_hist<<<(BATCH + 255) / 256, 256>>>(tgt);
    k_main<<<BATCH / ROWS, THREADS, SMEM_BYTES>>>(x);   // 1024 blocks
    k_final<<<40, 256>>>(out);
}